// round 4
// baseline (speedup 1.0000x reference)
#include <cuda_runtime.h>
#include <cuda_bf16.h>
#include <math.h>

// Problem constants
#define BB 128
#define SS 1024
#define IND 256
#define DD 128
#define MM 64
#define OUTD 128
#define NROWS (BB * SS)   // 131072

// Scratch. g_pack per (b,s): [0..64) w, [64..192) e, [192..320) a
__device__ float g_pack[(size_t)NROWS * 320];
__device__ float g_r[(size_t)NROWS * DD];
__device__ float g_wf[IND * MM];   // Wr @ MK^T  [256,64]
__device__ float g_bf[MM];         // br @ MK^T  [64]

// ---------------- f32x2 helpers ----------------
__device__ __forceinline__ unsigned long long f2fma(unsigned long long a,
                                                    unsigned long long b,
                                                    unsigned long long c) {
    unsigned long long d;
    asm("fma.rn.f32x2 %0, %1, %2, %3;" : "=l"(d) : "l"(a), "l"(b), "l"(c));
    return d;
}
__device__ __forceinline__ unsigned long long dup2(float x) {
    unsigned long long r;
    asm("mov.b64 %0, {%1, %1};" : "=l"(r) : "f"(x));
    return r;
}
__device__ __forceinline__ float lo32(unsigned long long v) {
    return __uint_as_float((unsigned)(v & 0xffffffffu));
}
__device__ __forceinline__ float hi32(unsigned long long v) {
    return __uint_as_float((unsigned)(v >> 32));
}

// ---------------- fast activations ----------------
__device__ __forceinline__ float fast_sigmoid(float v) {
    float t = __expf(-v);
    return __fdividef(1.0f, 1.0f + t);
}
__device__ __forceinline__ float fast_tanh(float v) {
    float t = __expf(fminf(2.0f * v, 80.0f));
    return __fdividef(t - 1.0f, t + 1.0f);
}

// =====================================================================
// Kernel 0: prep.  g_wf = Wr @ MK^T, g_bf = br @ MK^T.
// =====================================================================
__global__ __launch_bounds__(256) void prep_kernel(const float* __restrict__ Wr,
                                                   const float* __restrict__ br,
                                                   const float* __restrict__ mk) {
    int gid = blockIdx.x * 256 + threadIdx.x;
    int i = gid >> 6, m = gid & 63;
    float s = 0.f;
    const float* wr = Wr + i * 128;
    const float* mr = mk + m * 128;
#pragma unroll 4
    for (int d = 0; d < 128; d += 4) {
        float4 a = *(const float4*)(wr + d);
        float4 b = *(const float4*)(mr + d);
        s += a.x * b.x + a.y * b.y + a.z * b.z + a.w * b.w;
    }
    g_wf[i * 64 + m] = s;
    if (gid < 64) {
        float sb = 0.f;
        const float* mr2 = mk + gid * 128;
        for (int d = 0; d < 128; d++) sb += br[d] * mr2[d];
        g_bf[gid] = sb;
    }
}

// =====================================================================
// Kernel 1: v-projection with f32x2 FMAs. 128x128 tile, BK=16, 8x8/thread.
// =====================================================================
__global__ __launch_bounds__(256) void vproj_kernel(
    const float* __restrict__ x,
    const float* __restrict__ Ww, const float* __restrict__ bw) {
    __shared__ __align__(16) float As[16][132];
    __shared__ __align__(16) float Bs[16][128];

    const int row0 = blockIdx.x * 128;
    const int t = threadIdx.x;
    const int tm = (t >> 4) * 8;
    const int tn = (t & 15) * 8;

    unsigned long long acc2[8][4];
#pragma unroll
    for (int i = 0; i < 8; i++)
#pragma unroll
        for (int j = 0; j < 4; j++) acc2[i][j] = 0ULL;

    for (int k0 = 0; k0 < IND; k0 += 16) {
#pragma unroll
        for (int i = 0; i < 2; i++) {
            int idx = t + i * 256;
            int m  = idx >> 2;
            int kq = (idx & 3) * 4;
            float4 v = *(const float4*)(x + (size_t)(row0 + m) * IND + k0 + kq);
            As[kq + 0][m] = v.x; As[kq + 1][m] = v.y;
            As[kq + 2][m] = v.z; As[kq + 3][m] = v.w;
        }
#pragma unroll
        for (int i = 0; i < 2; i++) {
            int idx = t + i * 256;
            int kk = idx >> 5;
            int nq = (idx & 31) * 4;
            *(float4*)&Bs[kk][nq] = *(const float4*)(Ww + (size_t)(k0 + kk) * 128 + nq);
        }
        __syncthreads();
#pragma unroll
        for (int kk = 0; kk < 16; kk++) {
            float a[8];
            *(float4*)(a)     = *(const float4*)&As[kk][tm];
            *(float4*)(a + 4) = *(const float4*)&As[kk][tm + 4];
            unsigned long long b2[4];
            *(ulonglong2*)(b2)     = *(const ulonglong2*)&Bs[kk][tn];
            *(ulonglong2*)(b2 + 2) = *(const ulonglong2*)&Bs[kk][tn + 4];
#pragma unroll
            for (int i = 0; i < 8; i++) {
                unsigned long long ad = dup2(a[i]);
#pragma unroll
                for (int j = 0; j < 4; j++) acc2[i][j] = f2fma(ad, b2[j], acc2[i][j]);
            }
        }
        __syncthreads();
    }

    float bb[8];
    *(float4*)(bb)     = *(const float4*)(bw + tn);
    *(float4*)(bb + 4) = *(const float4*)(bw + tn + 4);

#pragma unroll
    for (int i = 0; i < 8; i++) {
        size_t row = (size_t)(row0 + tm + i);
        float e[8], av[8];
#pragma unroll
        for (int j = 0; j < 4; j++) {
            float v0 = lo32(acc2[i][j]) + bb[2 * j];
            float v1 = hi32(acc2[i][j]) + bb[2 * j + 1];
            e[2 * j]      = fast_sigmoid(v0);
            e[2 * j + 1]  = fast_sigmoid(v1);
            av[2 * j]     = fast_tanh(v0);
            av[2 * j + 1] = fast_tanh(v1);
        }
        float* pr = g_pack + row * 320;
        *(float4*)(pr + 64 + tn)      = *(float4*)(e);
        *(float4*)(pr + 64 + tn + 4)  = *(float4*)(e + 4);
        *(float4*)(pr + 192 + tn)     = *(float4*)(av);
        *(float4*)(pr + 192 + tn + 4) = *(float4*)(av + 4);
    }
}

// =====================================================================
// Kernel 2: w-projection + softmax with f32x2. 256x64 tile, 8x8/thread.
// =====================================================================
__global__ __launch_bounds__(256) void wproj_kernel(const float* __restrict__ x) {
    __shared__ __align__(16) float As[16][260];
    __shared__ __align__(16) float Bs[16][64];

    const int row0 = blockIdx.x * 256;
    const int t = threadIdx.x;
    const int tm = (t >> 3) * 8;
    const int tn = (t & 7) * 8;

    unsigned long long acc2[8][4];
#pragma unroll
    for (int i = 0; i < 8; i++)
#pragma unroll
        for (int j = 0; j < 4; j++) acc2[i][j] = 0ULL;

    for (int k0 = 0; k0 < IND; k0 += 16) {
#pragma unroll
        for (int u = 0; u < 4; u++) {
            int idx = t + u * 256;
            int m  = idx >> 2;
            int kq = (idx & 3) * 4;
            float4 v = *(const float4*)(x + (size_t)(row0 + m) * IND + k0 + kq);
            As[kq + 0][m] = v.x; As[kq + 1][m] = v.y;
            As[kq + 2][m] = v.z; As[kq + 3][m] = v.w;
        }
        {
            int kk = t >> 4;
            int nq = (t & 15) * 4;
            *(float4*)&Bs[kk][nq] = *(const float4*)(g_wf + (size_t)(k0 + kk) * 64 + nq);
        }
        __syncthreads();
#pragma unroll
        for (int kk = 0; kk < 16; kk++) {
            float a[8];
            *(float4*)(a)     = *(const float4*)&As[kk][tm];
            *(float4*)(a + 4) = *(const float4*)&As[kk][tm + 4];
            unsigned long long b2[4];
            *(ulonglong2*)(b2)     = *(const ulonglong2*)&Bs[kk][tn];
            *(ulonglong2*)(b2 + 2) = *(const ulonglong2*)&Bs[kk][tn + 4];
#pragma unroll
            for (int i = 0; i < 8; i++) {
                unsigned long long ad = dup2(a[i]);
#pragma unroll
                for (int j = 0; j < 4; j++) acc2[i][j] = f2fma(ad, b2[j], acc2[i][j]);
            }
        }
        __syncthreads();
    }

    float bb[8];
    *(float4*)(bb)     = *(const float4*)(g_bf + tn);
    *(float4*)(bb + 4) = *(const float4*)(g_bf + tn + 4);

#pragma unroll
    for (int i = 0; i < 8; i++) {
        float v[8];
        float mx = -1e30f;
#pragma unroll
        for (int j = 0; j < 4; j++) {
            v[2 * j]     = lo32(acc2[i][j]) + bb[2 * j];
            v[2 * j + 1] = hi32(acc2[i][j]) + bb[2 * j + 1];
            mx = fmaxf(mx, fmaxf(v[2 * j], v[2 * j + 1]));
        }
        mx = fmaxf(mx, __shfl_xor_sync(0xffffffffu, mx, 1));
        mx = fmaxf(mx, __shfl_xor_sync(0xffffffffu, mx, 2));
        mx = fmaxf(mx, __shfl_xor_sync(0xffffffffu, mx, 4));
        float s = 0.f;
#pragma unroll
        for (int j = 0; j < 8; j++) { v[j] = __expf(v[j] - mx); s += v[j]; }
        s += __shfl_xor_sync(0xffffffffu, s, 1);
        s += __shfl_xor_sync(0xffffffffu, s, 2);
        s += __shfl_xor_sync(0xffffffffu, s, 4);
        float inv = __fdividef(1.0f, s);
#pragma unroll
        for (int j = 0; j < 8; j++) v[j] *= inv;
        size_t row = (size_t)(row0 + tm + i);
        float* pr = g_pack + row * 320;
        *(float4*)(pr + tn)     = *(float4*)(v);
        *(float4*)(pr + tn + 4) = *(float4*)(v + 4);
    }
}

// =====================================================================
// Kernel 3: scan v3. 1024 threads/CTA, one CTA per batch, occ 50%.
// Thread t: dp = t>>4 (d = 2dp,2dp+1), mq = t&15, m in [4mq, 4mq+4).
// Mv: 4 packed f32x2 regs.
// SMEM slot (384 floats): [0..128) w pairs transposed: pair(m) at
//   (m&3)*16 + (m>>2)  -> 16 mq lanes read consecutive u64: conflict-free.
//   [128..256) e natural, [256..384) a natural.
// =====================================================================
__device__ __forceinline__ void stage_store3(float (*buf)[384], const float* v) {
    const int t = threadIdx.x;
#pragma unroll
    for (int k = 0; k < 2; k++) {
        int idx = t + 1024 * k;
        if (idx < 1280) {
            int q = idx / 320;
            int j = idx - q * 320;
            if (j < 64) {
                int pi = (j & 3) * 16 + (j >> 2);
                buf[q][2 * pi]     = v[k];
                buf[q][2 * pi + 1] = v[k];
            } else {
                buf[q][64 + j] = v[k];
            }
        }
    }
}

__global__ __launch_bounds__(1024) void scan_kernel(const float* __restrict__ mv0,
                                                    float* __restrict__ rout) {
    __shared__ __align__(16) float sbuf[2][4][384];
    const int b  = blockIdx.x;
    const int t  = threadIdx.x;
    const int dp = t >> 4;        // 0..63
    const int mq = t & 15;        // 0..15
    const int m0 = mq * 4;

    unsigned long long Mv[4];
#pragma unroll
    for (int i = 0; i < 4; i++)
        Mv[i] = *(const unsigned long long*)(mv0 + (m0 + i) * 128 + 2 * dp);

    const float* pk = g_pack + (size_t)b * (SS * 320);
    float stg[2];
#pragma unroll
    for (int k = 0; k < 2; k++) {
        int idx = t + 1024 * k;
        stg[k] = (idx < 1280) ? pk[idx] : 0.f;
    }
    stage_store3(sbuf[0], stg);
    __syncthreads();

    float* rb = rout + (size_t)b * (SS * 128) + 2 * dp;
    const int NCHUNK = SS / 4;

    for (int c = 0; c < NCHUNK; c++) {
        const int pb = c & 1;
        const bool more = (c + 1 < NCHUNK);
        if (more) {
            const float* pn = pk + (size_t)(c + 1) * 1280;
#pragma unroll
            for (int k = 0; k < 2; k++) {
                int idx = t + 1024 * k;
                if (idx < 1280) stg[k] = pn[idx];
            }
        }
#pragma unroll
        for (int q = 0; q < 4; q++) {
            const float* bq = sbuf[pb][q];
            unsigned long long e2 = *(const unsigned long long*)(bq + 128 + 2 * dp);
            unsigned long long a2 = *(const unsigned long long*)(bq + 256 + 2 * dp);
            unsigned long long ne2 = e2 ^ 0x8000000080000000ULL;
            unsigned long long r2a = 0ULL, r2b = 0ULL;
            {
                unsigned long long w0 = *(const unsigned long long*)(bq + 2 * (0 * 16 + mq));
                unsigned long long w1 = *(const unsigned long long*)(bq + 2 * (1 * 16 + mq));
                r2a = f2fma(w0, Mv[0], r2a);
                unsigned long long t0 = f2fma(ne2, Mv[0], a2);
                Mv[0] = f2fma(w0, t0, Mv[0]);
                r2b = f2fma(w1, Mv[1], r2b);
                unsigned long long t1 = f2fma(ne2, Mv[1], a2);
                Mv[1] = f2fma(w1, t1, Mv[1]);
                unsigned long long w2 = *(const unsigned long long*)(bq + 2 * (2 * 16 + mq));
                unsigned long long w3 = *(const unsigned long long*)(bq + 2 * (3 * 16 + mq));
                r2a = f2fma(w2, Mv[2], r2a);
                unsigned long long t2 = f2fma(ne2, Mv[2], a2);
                Mv[2] = f2fma(w2, t2, Mv[2]);
                r2b = f2fma(w3, Mv[3], r2b);
                unsigned long long t3 = f2fma(ne2, Mv[3], a2);
                Mv[3] = f2fma(w3, t3, Mv[3]);
            }
            float rx = lo32(r2a) + lo32(r2b);
            float ry = hi32(r2a) + hi32(r2b);
            rx += __shfl_xor_sync(0xffffffffu, rx, 1);
            ry += __shfl_xor_sync(0xffffffffu, ry, 1);
            rx += __shfl_xor_sync(0xffffffffu, rx, 2);
            ry += __shfl_xor_sync(0xffffffffu, ry, 2);
            rx += __shfl_xor_sync(0xffffffffu, rx, 4);
            ry += __shfl_xor_sync(0xffffffffu, ry, 4);
            rx += __shfl_xor_sync(0xffffffffu, rx, 8);
            ry += __shfl_xor_sync(0xffffffffu, ry, 8);
            if (mq == 0) {
                float2 rv; rv.x = rx; rv.y = ry;
                *(float2*)(rb + (size_t)(c * 4 + q) * 128) = rv;
            }
        }
        if (more) stage_store3(sbuf[pb ^ 1], stg);
        __syncthreads();
    }
}

// =====================================================================
// Kernel 4: y = sigmoid(r @ Wp + bp) with f32x2.
// =====================================================================
__global__ __launch_bounds__(256) void out_kernel(const float* __restrict__ Wp,
                                                  const float* __restrict__ bp,
                                                  float* __restrict__ out) {
    __shared__ __align__(16) float As[16][132];
    __shared__ __align__(16) float Bs[16][128];
    const int row0 = blockIdx.x * 128;
    const int t = threadIdx.x;
    const int tm = (t >> 4) * 8;
    const int tn = (t & 15) * 8;

    unsigned long long acc2[8][4];
#pragma unroll
    for (int i = 0; i < 8; i++)
#pragma unroll
        for (int j = 0; j < 4; j++) acc2[i][j] = 0ULL;

    for (int k0 = 0; k0 < DD; k0 += 16) {
#pragma unroll
        for (int i = 0; i < 2; i++) {
            int idx = t + i * 256;
            int m  = idx >> 2;
            int kq = (idx & 3) * 4;
            float4 v = *(const float4*)(g_r + (size_t)(row0 + m) * DD + k0 + kq);
            As[kq + 0][m] = v.x; As[kq + 1][m] = v.y;
            As[kq + 2][m] = v.z; As[kq + 3][m] = v.w;
        }
#pragma unroll
        for (int i = 0; i < 2; i++) {
            int idx = t + i * 256;
            int kk = idx >> 5;
            int nq = (idx & 31) * 4;
            *(float4*)&Bs[kk][nq] = *(const float4*)(Wp + (size_t)(k0 + kk) * 128 + nq);
        }
        __syncthreads();
#pragma unroll
        for (int kk = 0; kk < 16; kk++) {
            float a[8];
            *(float4*)(a)     = *(const float4*)&As[kk][tm];
            *(float4*)(a + 4) = *(const float4*)&As[kk][tm + 4];
            unsigned long long b2[4];
            *(ulonglong2*)(b2)     = *(const ulonglong2*)&Bs[kk][tn];
            *(ulonglong2*)(b2 + 2) = *(const ulonglong2*)&Bs[kk][tn + 4];
#pragma unroll
            for (int i = 0; i < 8; i++) {
                unsigned long long ad = dup2(a[i]);
#pragma unroll
                for (int j = 0; j < 4; j++) acc2[i][j] = f2fma(ad, b2[j], acc2[i][j]);
            }
        }
        __syncthreads();
    }

    float bb[8];
    *(float4*)(bb)     = *(const float4*)(bp + tn);
    *(float4*)(bb + 4) = *(const float4*)(bp + tn + 4);
#pragma unroll
    for (int i = 0; i < 8; i++) {
        size_t row = (size_t)(row0 + tm + i);
        float o[8];
#pragma unroll
        for (int j = 0; j < 4; j++) {
            o[2 * j]     = fast_sigmoid(lo32(acc2[i][j]) + bb[2 * j]);
            o[2 * j + 1] = fast_sigmoid(hi32(acc2[i][j]) + bb[2 * j + 1]);
        }
        *(float4*)(out + row * OUTD + tn)     = *(float4*)(o);
        *(float4*)(out + row * OUTD + tn + 4) = *(float4*)(o + 4);
    }
}

// =====================================================================
// Launch
// =====================================================================
extern "C" void kernel_launch(void* const* d_in, const int* in_sizes, int n_in,
                              void* d_out, int out_size) {
    const float* x   = (const float*)d_in[0];
    const float* mk  = (const float*)d_in[1];
    const float* mv  = (const float*)d_in[2];
    const float* Wr  = (const float*)d_in[3];
    const float* br  = (const float*)d_in[4];
    const float* Ww  = (const float*)d_in[5];
    const float* bw  = (const float*)d_in[6];
    const float* Wp  = (const float*)d_in[7];
    const float* bp  = (const float*)d_in[8];
    float* out = (float*)d_out;

    float* gr;
    cudaGetSymbolAddress((void**)&gr, g_r);

    prep_kernel<<<64, 256>>>(Wr, br, mk);
    vproj_kernel<<<NROWS / 128, 256>>>(x, Ww, bw);
    wproj_kernel<<<NROWS / 256, 256>>>(x);
    scan_kernel<<<BB, 1024>>>(mv, gr);
    out_kernel<<<NROWS / 128, 256>>>(Wp, bp, out);
}

// round 5
// speedup vs baseline: 1.1405x; 1.1405x over previous
#include <cuda_runtime.h>
#include <cuda_bf16.h>
#include <math.h>

// Problem constants
#define BB 128
#define SS 1024
#define IND 256
#define DD 128
#define MM 64
#define OUTD 128
#define NROWS (BB * SS)   // 131072

// Scratch. g_pack per (b,s): [0..64) w, [64..192) e, [192..320) a
__device__ float g_pack[(size_t)NROWS * 320];
__device__ float g_r[(size_t)NROWS * DD];
__device__ float g_wf[IND * MM];   // Wr @ MK^T  [256,64]
__device__ float g_bf[MM];         // br @ MK^T  [64]

// ---------------- f32x2 helpers ----------------
__device__ __forceinline__ unsigned long long f2fma(unsigned long long a,
                                                    unsigned long long b,
                                                    unsigned long long c) {
    unsigned long long d;
    asm("fma.rn.f32x2 %0, %1, %2, %3;" : "=l"(d) : "l"(a), "l"(b), "l"(c));
    return d;
}
__device__ __forceinline__ unsigned long long dup2(float x) {
    unsigned long long r;
    asm("mov.b64 %0, {%1, %1};" : "=l"(r) : "f"(x));
    return r;
}
__device__ __forceinline__ float lo32(unsigned long long v) {
    return __uint_as_float((unsigned)(v & 0xffffffffu));
}
__device__ __forceinline__ float hi32(unsigned long long v) {
    return __uint_as_float((unsigned)(v >> 32));
}

// ---------------- fast activations ----------------
__device__ __forceinline__ float fast_sigmoid(float v) {
    float t = __expf(-v);
    return __fdividef(1.0f, 1.0f + t);
}
__device__ __forceinline__ float fast_tanh(float v) {
    float t = __expf(fminf(2.0f * v, 80.0f));
    return __fdividef(t - 1.0f, t + 1.0f);
}

// =====================================================================
// Kernel 0: prep.  g_wf = Wr @ MK^T, g_bf = br @ MK^T.
// =====================================================================
__global__ __launch_bounds__(256) void prep_kernel(const float* __restrict__ Wr,
                                                   const float* __restrict__ br,
                                                   const float* __restrict__ mk) {
    int gid = blockIdx.x * 256 + threadIdx.x;
    int i = gid >> 6, m = gid & 63;
    float s = 0.f;
    const float* wr = Wr + i * 128;
    const float* mr = mk + m * 128;
#pragma unroll 4
    for (int d = 0; d < 128; d += 4) {
        float4 a = *(const float4*)(wr + d);
        float4 b = *(const float4*)(mr + d);
        s += a.x * b.x + a.y * b.y + a.z * b.z + a.w * b.w;
    }
    g_wf[i * 64 + m] = s;
    if (gid < 64) {
        float sb = 0.f;
        const float* mr2 = mk + gid * 128;
        for (int d = 0; d < 128; d++) sb += br[d] * mr2[d];
        g_bf[gid] = sb;
    }
}

// =====================================================================
// Kernel 1: v-projection with f32x2 FMAs. 128x128 tile, BK=16, 8x8/thread.
// =====================================================================
__global__ __launch_bounds__(256) void vproj_kernel(
    const float* __restrict__ x,
    const float* __restrict__ Ww, const float* __restrict__ bw) {
    __shared__ __align__(16) float As[16][132];
    __shared__ __align__(16) float Bs[16][128];

    const int row0 = blockIdx.x * 128;
    const int t = threadIdx.x;
    const int tm = (t >> 4) * 8;
    const int tn = (t & 15) * 8;

    unsigned long long acc2[8][4];
#pragma unroll
    for (int i = 0; i < 8; i++)
#pragma unroll
        for (int j = 0; j < 4; j++) acc2[i][j] = 0ULL;

    for (int k0 = 0; k0 < IND; k0 += 16) {
#pragma unroll
        for (int i = 0; i < 2; i++) {
            int idx = t + i * 256;
            int m  = idx >> 2;
            int kq = (idx & 3) * 4;
            float4 v = *(const float4*)(x + (size_t)(row0 + m) * IND + k0 + kq);
            As[kq + 0][m] = v.x; As[kq + 1][m] = v.y;
            As[kq + 2][m] = v.z; As[kq + 3][m] = v.w;
        }
#pragma unroll
        for (int i = 0; i < 2; i++) {
            int idx = t + i * 256;
            int kk = idx >> 5;
            int nq = (idx & 31) * 4;
            *(float4*)&Bs[kk][nq] = *(const float4*)(Ww + (size_t)(k0 + kk) * 128 + nq);
        }
        __syncthreads();
#pragma unroll
        for (int kk = 0; kk < 16; kk++) {
            float a[8];
            *(float4*)(a)     = *(const float4*)&As[kk][tm];
            *(float4*)(a + 4) = *(const float4*)&As[kk][tm + 4];
            unsigned long long b2[4];
            *(ulonglong2*)(b2)     = *(const ulonglong2*)&Bs[kk][tn];
            *(ulonglong2*)(b2 + 2) = *(const ulonglong2*)&Bs[kk][tn + 4];
#pragma unroll
            for (int i = 0; i < 8; i++) {
                unsigned long long ad = dup2(a[i]);
#pragma unroll
                for (int j = 0; j < 4; j++) acc2[i][j] = f2fma(ad, b2[j], acc2[i][j]);
            }
        }
        __syncthreads();
    }

    float bb[8];
    *(float4*)(bb)     = *(const float4*)(bw + tn);
    *(float4*)(bb + 4) = *(const float4*)(bw + tn + 4);

#pragma unroll
    for (int i = 0; i < 8; i++) {
        size_t row = (size_t)(row0 + tm + i);
        float e[8], av[8];
#pragma unroll
        for (int j = 0; j < 4; j++) {
            float v0 = lo32(acc2[i][j]) + bb[2 * j];
            float v1 = hi32(acc2[i][j]) + bb[2 * j + 1];
            e[2 * j]      = fast_sigmoid(v0);
            e[2 * j + 1]  = fast_sigmoid(v1);
            av[2 * j]     = fast_tanh(v0);
            av[2 * j + 1] = fast_tanh(v1);
        }
        float* pr = g_pack + row * 320;
        *(float4*)(pr + 64 + tn)      = *(float4*)(e);
        *(float4*)(pr + 64 + tn + 4)  = *(float4*)(e + 4);
        *(float4*)(pr + 192 + tn)     = *(float4*)(av);
        *(float4*)(pr + 192 + tn + 4) = *(float4*)(av + 4);
    }
}

// =====================================================================
// Kernel 2: w-projection + softmax with f32x2. 256x64 tile, 8x8/thread.
// =====================================================================
__global__ __launch_bounds__(256) void wproj_kernel(const float* __restrict__ x) {
    __shared__ __align__(16) float As[16][260];
    __shared__ __align__(16) float Bs[16][64];

    const int row0 = blockIdx.x * 256;
    const int t = threadIdx.x;
    const int tm = (t >> 3) * 8;
    const int tn = (t & 7) * 8;

    unsigned long long acc2[8][4];
#pragma unroll
    for (int i = 0; i < 8; i++)
#pragma unroll
        for (int j = 0; j < 4; j++) acc2[i][j] = 0ULL;

    for (int k0 = 0; k0 < IND; k0 += 16) {
#pragma unroll
        for (int u = 0; u < 4; u++) {
            int idx = t + u * 256;
            int m  = idx >> 2;
            int kq = (idx & 3) * 4;
            float4 v = *(const float4*)(x + (size_t)(row0 + m) * IND + k0 + kq);
            As[kq + 0][m] = v.x; As[kq + 1][m] = v.y;
            As[kq + 2][m] = v.z; As[kq + 3][m] = v.w;
        }
        {
            int kk = t >> 4;
            int nq = (t & 15) * 4;
            *(float4*)&Bs[kk][nq] = *(const float4*)(g_wf + (size_t)(k0 + kk) * 64 + nq);
        }
        __syncthreads();
#pragma unroll
        for (int kk = 0; kk < 16; kk++) {
            float a[8];
            *(float4*)(a)     = *(const float4*)&As[kk][tm];
            *(float4*)(a + 4) = *(const float4*)&As[kk][tm + 4];
            unsigned long long b2[4];
            *(ulonglong2*)(b2)     = *(const ulonglong2*)&Bs[kk][tn];
            *(ulonglong2*)(b2 + 2) = *(const ulonglong2*)&Bs[kk][tn + 4];
#pragma unroll
            for (int i = 0; i < 8; i++) {
                unsigned long long ad = dup2(a[i]);
#pragma unroll
                for (int j = 0; j < 4; j++) acc2[i][j] = f2fma(ad, b2[j], acc2[i][j]);
            }
        }
        __syncthreads();
    }

    float bb[8];
    *(float4*)(bb)     = *(const float4*)(g_bf + tn);
    *(float4*)(bb + 4) = *(const float4*)(g_bf + tn + 4);

#pragma unroll
    for (int i = 0; i < 8; i++) {
        float v[8];
        float mx = -1e30f;
#pragma unroll
        for (int j = 0; j < 4; j++) {
            v[2 * j]     = lo32(acc2[i][j]) + bb[2 * j];
            v[2 * j + 1] = hi32(acc2[i][j]) + bb[2 * j + 1];
            mx = fmaxf(mx, fmaxf(v[2 * j], v[2 * j + 1]));
        }
        mx = fmaxf(mx, __shfl_xor_sync(0xffffffffu, mx, 1));
        mx = fmaxf(mx, __shfl_xor_sync(0xffffffffu, mx, 2));
        mx = fmaxf(mx, __shfl_xor_sync(0xffffffffu, mx, 4));
        float s = 0.f;
#pragma unroll
        for (int j = 0; j < 8; j++) { v[j] = __expf(v[j] - mx); s += v[j]; }
        s += __shfl_xor_sync(0xffffffffu, s, 1);
        s += __shfl_xor_sync(0xffffffffu, s, 2);
        s += __shfl_xor_sync(0xffffffffu, s, 4);
        float inv = __fdividef(1.0f, s);
#pragma unroll
        for (int j = 0; j < 8; j++) v[j] *= inv;
        size_t row = (size_t)(row0 + tm + i);
        float* pr = g_pack + row * 320;
        *(float4*)(pr + tn)     = *(float4*)(v);
        *(float4*)(pr + tn + 4) = *(float4*)(v + 4);
    }
}

// =====================================================================
// Kernel 3: scan v4. Grid (BB, 2): batch b, d-half h. 256 threads/CTA.
// Thread t: dpl = t>>3 (local d-pair 0..31, global d = 64h + 2dpl),
//           mq = t&7, m in [8mq, 8mq+8). Mv: 8 packed f32x2 regs.
// Chunk = 8 steps, double-buffered. SMEM slot = 256 floats:
//   [0..128)  w pairs transposed: pair(m) at i*8+mq for m=8mq+i -> conflict-free
//   [128..192) e slice (this CTA's 64 d's), [192..256) a slice.
// =====================================================================
__device__ __forceinline__ void stage_store4(float (*buf)[256], const float* v) {
    const int t = threadIdx.x;
#pragma unroll
    for (int k = 0; k < 6; k++) {
        int idx = t + 256 * k;           // 0..1535
        int q = idx / 192;               // step in chunk 0..7
        int j = idx - q * 192;           // 0..191
        if (j < 64) {
            int pi = (j & 7) * 8 + (j >> 3);
            buf[q][2 * pi]     = v[k];
            buf[q][2 * pi + 1] = v[k];
        } else {
            buf[q][64 + j] = v[k];       // e -> [128..192), a -> [192..256)
        }
    }
}

__global__ __launch_bounds__(256) void scan_kernel(const float* __restrict__ mv0,
                                                   float* __restrict__ rout) {
    __shared__ __align__(16) float sbuf[2][8][256];
    const int b   = blockIdx.x;
    const int h   = blockIdx.y;          // d-half
    const int t   = threadIdx.x;
    const int dpl = t >> 3;              // 0..31
    const int mq  = t & 7;               // 0..7
    const int m0  = mq * 8;
    const int dof = 64 * h + 2 * dpl;    // global d offset of this thread's pair

    unsigned long long Mv[8];
#pragma unroll
    for (int i = 0; i < 8; i++)
        Mv[i] = *(const unsigned long long*)(mv0 + (m0 + i) * 128 + dof);

    const float* pk = g_pack + (size_t)b * (SS * 320);

    // gmem gather for staging: idx -> step q, element j
    // j<64: w[j]; 64<=j<128: e[64h + j-64] at pack 64+64h+(j-64) = j + 64h
    // 128<=j<192: a[...] at pack 192+64h+(j-128) = j + 64 + 64h
    float stg[6];
#pragma unroll
    for (int k = 0; k < 6; k++) {
        int idx = t + 256 * k;
        int q = idx / 192;
        int j = idx - q * 192;
        int goff = (j < 64) ? j : ((j < 128) ? (j + 64 * h) : (j + 64 + 64 * h));
        stg[k] = pk[q * 320 + goff];
    }
    stage_store4(sbuf[0], stg);
    __syncthreads();

    float* rb = rout + (size_t)b * (SS * 128) + dof;
    const int NCHUNK = SS / 8;

    for (int c = 0; c < NCHUNK; c++) {
        const int pb = c & 1;
        const bool more = (c + 1 < NCHUNK);
        if (more) {
            const float* pn = pk + (size_t)(c + 1) * (8 * 320);
#pragma unroll
            for (int k = 0; k < 6; k++) {
                int idx = t + 256 * k;
                int q = idx / 192;
                int j = idx - q * 192;
                int goff = (j < 64) ? j : ((j < 128) ? (j + 64 * h) : (j + 64 + 64 * h));
                stg[k] = pn[q * 320 + goff];
            }
        }
#pragma unroll
        for (int q = 0; q < 8; q++) {
            const float* bq = sbuf[pb][q];
            unsigned long long e2 = *(const unsigned long long*)(bq + 128 + 2 * dpl);
            unsigned long long a2 = *(const unsigned long long*)(bq + 192 + 2 * dpl);
            unsigned long long ne2 = e2 ^ 0x8000000080000000ULL;
            unsigned long long r2a = 0ULL, r2b = 0ULL;
#pragma unroll
            for (int i = 0; i < 8; i += 2) {
                unsigned long long w0 = *(const unsigned long long*)(bq + 2 * ((i    ) * 8 + mq));
                unsigned long long w1 = *(const unsigned long long*)(bq + 2 * ((i + 1) * 8 + mq));
                r2a = f2fma(w0, Mv[i], r2a);
                unsigned long long t0 = f2fma(ne2, Mv[i], a2);
                Mv[i] = f2fma(w0, t0, Mv[i]);
                r2b = f2fma(w1, Mv[i + 1], r2b);
                unsigned long long t1 = f2fma(ne2, Mv[i + 1], a2);
                Mv[i + 1] = f2fma(w1, t1, Mv[i + 1]);
            }
            float rx = lo32(r2a) + lo32(r2b);
            float ry = hi32(r2a) + hi32(r2b);
            rx += __shfl_xor_sync(0xffffffffu, rx, 1);
            ry += __shfl_xor_sync(0xffffffffu, ry, 1);
            rx += __shfl_xor_sync(0xffffffffu, rx, 2);
            ry += __shfl_xor_sync(0xffffffffu, ry, 2);
            rx += __shfl_xor_sync(0xffffffffu, rx, 4);
            ry += __shfl_xor_sync(0xffffffffu, ry, 4);
            if (mq == 0) {
                float2 rv; rv.x = rx; rv.y = ry;
                *(float2*)(rb + (size_t)(c * 8 + q) * 128) = rv;
            }
        }
        if (more) stage_store4(sbuf[pb ^ 1], stg);
        __syncthreads();
    }
}

// =====================================================================
// Kernel 4: y = sigmoid(r @ Wp + bp) with f32x2.
// =====================================================================
__global__ __launch_bounds__(256) void out_kernel(const float* __restrict__ Wp,
                                                  const float* __restrict__ bp,
                                                  float* __restrict__ out) {
    __shared__ __align__(16) float As[16][132];
    __shared__ __align__(16) float Bs[16][128];
    const int row0 = blockIdx.x * 128;
    const int t = threadIdx.x;
    const int tm = (t >> 4) * 8;
    const int tn = (t & 15) * 8;

    unsigned long long acc2[8][4];
#pragma unroll
    for (int i = 0; i < 8; i++)
#pragma unroll
        for (int j = 0; j < 4; j++) acc2[i][j] = 0ULL;

    for (int k0 = 0; k0 < DD; k0 += 16) {
#pragma unroll
        for (int i = 0; i < 2; i++) {
            int idx = t + i * 256;
            int m  = idx >> 2;
            int kq = (idx & 3) * 4;
            float4 v = *(const float4*)(g_r + (size_t)(row0 + m) * DD + k0 + kq);
            As[kq + 0][m] = v.x; As[kq + 1][m] = v.y;
            As[kq + 2][m] = v.z; As[kq + 3][m] = v.w;
        }
#pragma unroll
        for (int i = 0; i < 2; i++) {
            int idx = t + i * 256;
            int kk = idx >> 5;
            int nq = (idx & 31) * 4;
            *(float4*)&Bs[kk][nq] = *(const float4*)(Wp + (size_t)(k0 + kk) * 128 + nq);
        }
        __syncthreads();
#pragma unroll
        for (int kk = 0; kk < 16; kk++) {
            float a[8];
            *(float4*)(a)     = *(const float4*)&As[kk][tm];
            *(float4*)(a + 4) = *(const float4*)&As[kk][tm + 4];
            unsigned long long b2[4];
            *(ulonglong2*)(b2)     = *(const ulonglong2*)&Bs[kk][tn];
            *(ulonglong2*)(b2 + 2) = *(const ulonglong2*)&Bs[kk][tn + 4];
#pragma unroll
            for (int i = 0; i < 8; i++) {
                unsigned long long ad = dup2(a[i]);
#pragma unroll
                for (int j = 0; j < 4; j++) acc2[i][j] = f2fma(ad, b2[j], acc2[i][j]);
            }
        }
        __syncthreads();
    }

    float bb[8];
    *(float4*)(bb)     = *(const float4*)(bp + tn);
    *(float4*)(bb + 4) = *(const float4*)(bp + tn + 4);
#pragma unroll
    for (int i = 0; i < 8; i++) {
        size_t row = (size_t)(row0 + tm + i);
        float o[8];
#pragma unroll
        for (int j = 0; j < 4; j++) {
            o[2 * j]     = fast_sigmoid(lo32(acc2[i][j]) + bb[2 * j]);
            o[2 * j + 1] = fast_sigmoid(hi32(acc2[i][j]) + bb[2 * j + 1]);
        }
        *(float4*)(out + row * OUTD + tn)     = *(float4*)(o);
        *(float4*)(out + row * OUTD + tn + 4) = *(float4*)(o + 4);
    }
}

// =====================================================================
// Launch
// =====================================================================
extern "C" void kernel_launch(void* const* d_in, const int* in_sizes, int n_in,
                              void* d_out, int out_size) {
    const float* x   = (const float*)d_in[0];
    const float* mk  = (const float*)d_in[1];
    const float* mv  = (const float*)d_in[2];
    const float* Wr  = (const float*)d_in[3];
    const float* br  = (const float*)d_in[4];
    const float* Ww  = (const float*)d_in[5];
    const float* bw  = (const float*)d_in[6];
    const float* Wp  = (const float*)d_in[7];
    const float* bp  = (const float*)d_in[8];
    float* out = (float*)d_out;

    float* gr;
    cudaGetSymbolAddress((void**)&gr, g_r);

    prep_kernel<<<64, 256>>>(Wr, br, mk);
    vproj_kernel<<<NROWS / 128, 256>>>(x, Ww, bw);
    wproj_kernel<<<NROWS / 256, 256>>>(x);
    scan_kernel<<<dim3(BB, 2), 256>>>(mv, gr);
    out_kernel<<<NROWS / 128, 256>>>(Wp, bp, out);
}